// round 15
// baseline (speedup 1.0000x reference)
#include <cuda_runtime.h>
#include <cuda_fp16.h>

// ---------------------------------------------------------------------------
// WavePlaneField: 6 planes reconstructed via 2-level inverse DWT (coif4,
// periodization), bilinear-sampled at N points, channelwise product.
//
// Phase 1 (3 kernels):
//   k_s12: fused level-1 synthesis (H then W) per (plane, channel); lo1/hi1
//          staged in smem (kills 12x global read amplification of stage2).
//   k_s3t: tiled level-2 H synthesis per (plane, channel, x-tile); mid+yha
//          staged in smem (kills 12x global read amplification of stage3).
//   k_stage4: row-tiled W synthesis + transpose to x-paired fp16 planes.
// Phase 2: warp-per-point sampler; lanes 0-5 compute the 6 planes' coords
//   in parallel, shfl broadcast, 12 half2 loads + fp32 interp + product.
// ---------------------------------------------------------------------------

#define CCH 32

// All planes have H=256. W per plane:
__constant__ int c_W[6]    = {256, 256, 64, 256, 64, 64};
__constant__ int c_POFF[6] = {0, 65536, 131072, 147456, 212992, 229376}; // pixel offsets

// coif4 reconstruction filters (24 taps)
__constant__ float REC_LO_C[24] = {
    0.0008923136685823146f, -0.0016294920126017326f, -0.0073461663276420935f,
    0.016068943964776348f, 0.026682300156053072f, -0.08126669968087875f,
    -0.05607731331675481f, 0.41530840703043026f, 0.782238930920499f,
    0.4343860564914685f, -0.06662747426342504f, -0.09622044203398798f,
    0.03933442712333749f, 0.025082261844864097f, -0.015211731527946259f,
    -0.00565828668661072f, 0.003751436157278457f, 0.0012665619292989445f,
    -0.0005890207562443383f, -0.00025997455248771324f, 6.233903446100713e-05f,
    3.1229875865345646e-05f, -3.2596802368833675e-06f, -1.7849850030882614e-06f
};
__constant__ float REC_HI_C[24] = {
    -1.7849850030882614e-06f, 3.2596802368833675e-06f, 3.1229875865345646e-05f,
    -6.233903446100713e-05f, -0.00025997455248771324f, 0.0005890207562443383f,
    0.0012665619292989445f, -0.003751436157278457f, -0.00565828668661072f,
    0.015211731527946259f, 0.025082261844864097f, -0.03933442712333749f,
    -0.09622044203398798f, 0.06662747426342504f, 0.4343860564914685f,
    -0.782238930920499f, 0.41530840703043026f, 0.05607731331675481f,
    -0.08126669968087875f, -0.026682300156053072f, 0.016068943964776348f,
    0.0073461663276420935f, -0.0016294920126017326f, -0.0008923136685823146f
};

// Scratch (static device globals)
#define S_MID 524288    // C*128*128
#define S_LO2 1048576   // C*256*128
__device__ float g_mid[6 * S_MID];
__device__ float g_lo2[6 * S_LO2];
__device__ float g_hi2[6 * S_LO2];
// x-paired fp16 planes: [pixel][c] = half2(v[y,x,c], v[y,min(x+1,W-1),c])
__device__ __half2 g_planes2[245760 * CCH];

struct CoefPtrs {
    const float* yl[6];
    const float* yha[6];
    const float* yhb[6];
};

// ---------------------------------------------------------------------------
// k_s12: fused level-1 synthesis. Block per (channel=blockIdx.x, plane=y).
// Phase A (paired-parity H synthesis): global yl/yhb -> smem lo1/hi1 [128][w4].
// Phase B (paired-parity W synthesis): smem -> g_mid [C,128,w2].
// Dynamic smem: 2 * 128 * w4max(64) * 4B = 64 KB.
// ---------------------------------------------------------------------------
__global__ void __launch_bounds__(256) k_s12(CoefPtrs P) {
    const int pl = blockIdx.y;
    const int c  = blockIdx.x;
    const int w4 = c_W[pl] >> 2;
    const int w2 = w4 << 1;

    extern __shared__ float sm[];
    float* lo1 = sm;                 // [128][w4]
    float* hi1 = sm + 128 * w4;      // [128][w4]

    const float* yl  = P.yl[pl];
    const float* yhb = P.yhb[pl];
    const int bandStride = 64 * w4;

    // Phase A: output row-pairs s=0..63, x=0..w4-1
    for (int t = threadIdx.x; t < 64 * w4; t += 256) {
        const int x = t % w4;
        const int s = t / w4;
        float lo0 = 0.f, lo1v = 0.f, hi0 = 0.f, hi1v = 0.f;
#pragma unroll
        for (int m = 0; m < 12; m++) {
            int row = s - m; if (row < 0) row += 64;
            const float a  = yl [(c * 64 + row) * w4 + x];
            const int b0i  = ((c * 3 + 0) * 64 + row) * w4 + x;
            const float b0 = yhb[b0i];
            const float b1 = yhb[b0i + bandStride];
            const float b2 = yhb[b0i + 2 * bandStride];
            const float fl0 = REC_LO_C[2 * m],     fh0 = REC_HI_C[2 * m];
            const float fl1 = REC_LO_C[2 * m + 1], fh1 = REC_HI_C[2 * m + 1];
            lo0  += fl0 * a  + fh0 * b0;
            lo1v += fl1 * a  + fh1 * b0;
            hi0  += fl0 * b1 + fh0 * b2;
            hi1v += fl1 * b1 + fh1 * b2;
        }
        lo1[(2 * s) * w4 + x]     = lo0;
        lo1[(2 * s + 1) * w4 + x] = lo1v;
        hi1[(2 * s) * w4 + x]     = hi0;
        hi1[(2 * s + 1) * w4 + x] = hi1v;
    }
    __syncthreads();

    // Phase B: output col-pairs s=0..w4-1 for each of 128 rows
    float* midOut = g_mid + pl * S_MID + c * 128 * w2;
    for (int t = threadIdx.x; t < 128 * w4; t += 256) {
        const int s = t % w4;
        const int i = t / w4;
        const float* lp = lo1 + i * w4;
        const float* hp = hi1 + i * w4;
        float v0 = 0.f, v1 = 0.f;
#pragma unroll
        for (int m = 0; m < 12; m++) {
            int col = s - m; if (col < 0) col += w4;
            const float lv = lp[col];
            const float hv = hp[col];
            v0 += REC_LO_C[2 * m]     * lv + REC_HI_C[2 * m]     * hv;
            v1 += REC_LO_C[2 * m + 1] * lv + REC_HI_C[2 * m + 1] * hv;
        }
        midOut[i * w2 + 2 * s]     = v0;
        midOut[i * w2 + 2 * s + 1] = v1;
    }
}

// ---------------------------------------------------------------------------
// k_s3t: tiled level-2 H synthesis. Block per (x-tile=blockIdx.x, c=y, pl=z).
// Stages mid[c][0..127][tile32] + 3 yha bands in smem (each element read from
// global exactly once), then paired-parity column synthesis -> lo2,hi2.
// Dynamic smem: 4 * 128 * 32 * 4B = 64 KB.
// ---------------------------------------------------------------------------
__global__ void __launch_bounds__(256) k_s3t(CoefPtrs P) {
    const int pl = blockIdx.z;
    const int c  = blockIdx.y;
    const int w2 = c_W[pl] >> 1;
    const int x0 = blockIdx.x * 32;
    if (x0 >= w2) return;

    extern __shared__ float sm[];
    float* mid_s = sm;                // [128][32]
    float* a0_s  = sm + 128 * 32;     // [128][32]
    float* a1_s  = sm + 2 * 128 * 32;
    float* a2_s  = sm + 3 * 128 * 32;

    const float* yha = P.yha[pl];
    const int bandStride = 128 * w2;
    const float* midP = g_mid + pl * S_MID;

    for (int t = threadIdx.x; t < 128 * 32; t += 256) {
        const int x = t & 31;
        const int row = t >> 5;
        mid_s[t] = midP[(c * 128 + row) * w2 + x0 + x];
        const int ai = ((c * 3 + 0) * 128 + row) * w2 + x0 + x;
        a0_s[t] = yha[ai];
        a1_s[t] = yha[ai + bandStride];
        a2_s[t] = yha[ai + 2 * bandStride];
    }
    __syncthreads();

    float* lo2Out = g_lo2 + pl * S_LO2 + c * 256 * w2 + x0;
    float* hi2Out = g_hi2 + pl * S_LO2 + c * 256 * w2 + x0;
    // output row-pairs s=0..127, x=0..31
    for (int t = threadIdx.x; t < 128 * 32; t += 256) {
        const int x = t & 31;
        const int s = t >> 5;
        float lo0 = 0.f, lo1v = 0.f, hi0 = 0.f, hi1v = 0.f;
#pragma unroll
        for (int m = 0; m < 12; m++) {
            int row = s - m; if (row < 0) row += 128;
            const int si = row * 32 + x;
            const float mv = mid_s[si];
            const float a0 = a0_s[si];
            const float a1 = a1_s[si];
            const float a2 = a2_s[si];
            const float fl0 = REC_LO_C[2 * m],     fh0 = REC_HI_C[2 * m];
            const float fl1 = REC_LO_C[2 * m + 1], fh1 = REC_HI_C[2 * m + 1];
            lo0  += fl0 * mv + fh0 * a0;
            lo1v += fl1 * mv + fh1 * a0;
            hi0  += fl0 * a1 + fh0 * a2;
            hi1v += fl1 * a1 + fh1 * a2;
        }
        lo2Out[(2 * s) * w2 + x]     = lo0;
        lo2Out[(2 * s + 1) * w2 + x] = lo1v;
        hi2Out[(2 * s) * w2 + x]     = hi0;
        hi2Out[(2 * s + 1) * w2 + x] = hi1v;
    }
}

// Stage 4 (row-tiled, paired-parity, wrap-padded smem, x-paired output):
// level-2 W-axis synthesis + transpose to x-paired half2 layout.
__global__ void __launch_bounds__(256) k_stage4() {
    const int pl = blockIdx.y;
    const int W = c_W[pl];
    const int w2 = W >> 1;
    const int y = blockIdx.x;

    __shared__ float lo_s[32][141];    // [c][11 wrap pads | w2 cols]
    __shared__ float hi_s[32][141];
    __shared__ float out_s[256][33];   // [x][c]

    const int sh = (w2 == 128) ? 7 : 5;          // log2(w2)
    const int rowBase = pl * S_LO2 + y * w2;     // + c*256*w2 per channel
    for (int t = threadIdx.x; t < 32 * w2; t += 256) {
        const int c = t >> sh;
        const int col = t & (w2 - 1);
        const int gi = rowBase + c * (256 * w2) + col;
        lo_s[c][11 + col] = g_lo2[gi];
        hi_s[c][11 + col] = g_hi2[gi];
    }
    // wrap pads: k=0..10 holds logical col w2-11+k
    for (int t = threadIdx.x; t < 32 * 11; t += 256) {
        const int c = t / 11;
        const int k = t % 11;
        const int gi = rowBase + c * (256 * w2) + (w2 - 11 + k);
        lo_s[c][k] = g_lo2[gi];
        hi_s[c][k] = g_hi2[gi];
    }
    __syncthreads();

    const int nPairs = w2 * CCH;                  // one thread -> 2 outputs
    for (int t = threadIdx.x; t < nPairs; t += 256) {
        const int c = t & 31;
        const int s = t >> 5;
        const float* lp = &lo_s[c][11 + s];       // taps at lp[-m]
        const float* hp = &hi_s[c][11 + s];
        float v0 = 0.f, v1 = 0.f;                 // parity 0 / parity 1
#pragma unroll
        for (int m = 0; m < 12; m++) {
            const float lv = lp[-m];
            const float hv = hp[-m];
            v0 += REC_LO_C[2 * m]     * lv + REC_HI_C[2 * m]     * hv;
            v1 += REC_LO_C[2 * m + 1] * lv + REC_HI_C[2 * m + 1] * hv;
        }
        out_s[2 * s][c]     = v0;
        out_s[2 * s + 1][c] = v1;
    }
    __syncthreads();

    __half2* __restrict__ outRow = g_planes2 + ((size_t)(c_POFF[pl] + y * W)) * CCH;
    const int n = W * CCH;
    for (int t = threadIdx.x; t < n; t += 256) {
        const int c = t & 31;
        const int x = t >> 5;
        const int x1 = (x + 1 < W) ? x + 1 : W - 1;
        outRow[x * CCH + c] = __floats2half2_rn(out_s[x][c], out_s[x1][c]);
    }
}

// Phase 2: warp per point, lane = channel. Lanes 0-5 compute the 6 planes'
// coords IN PARALLEL; shfl broadcasts (base, wx, wy); 12 half2 loads +
// fp32 interp + product.
__global__ void __launch_bounds__(256) k_sample(const float* __restrict__ pts,
                                                const float* __restrict__ ts,
                                                float* __restrict__ out,
                                                int nPts) {
    const int warp = (blockIdx.x * blockDim.x + threadIdx.x) >> 5;
    const int lane = threadIdx.x & 31;
    if (warp >= nPts) return;

    const float inv = -1.0f / 1.3f;   // pts_n = -pts/B
    const float p0 = pts[warp * 3 + 0] * inv;
    const float p1 = pts[warp * 3 + 1] * inv;
    const float p2 = pts[warp * 3 + 2] * inv;
    const float p3 = ts[warp] * 2.0f - 1.0f;

    // Per-lane plane coords (lanes 0-5 meaningful):
    // QIDX = {0,0,3,1,3,3} -> cx; RIDX = {1,2,0,2,1,2} -> cy
    const float cx = (lane < 2) ? p0 : ((lane == 3) ? p1 : p3);
    const float cy = (lane == 0 || lane == 4) ? p1
                   : ((lane == 2) ? p0 : p2);
    // W per plane {256,256,64,256,64,64}
    const bool small = (lane == 2 || lane >= 4);
    const float Wm1 = small ? 63.0f : 255.0f;
    const int   Wi  = small ? 64 : 256;
    const int   poff = c_POFF[(lane < 6) ? lane : 0];

    float xf = fminf(fmaxf((cx + 1.0f) * 0.5f * Wm1, 0.0f), Wm1);
    float yf = fminf(fmaxf((cy + 1.0f) * 0.5f * 255.0f, 0.0f), 255.0f);
    float x0f = fminf(floorf(xf), Wm1 - 1.0f);   // xf >= 0 already
    float y0f = fminf(floorf(yf), 254.0f);
    const float wx = xf - x0f;
    const float wy = yf - y0f;
    const int  base = (poff + (int)y0f * Wi + (int)x0f) * CCH;

    constexpr int PW[6] = {256, 256, 64, 256, 64, 64};

    float prod = 1.0f;
#pragma unroll
    for (int ii = 0; ii < 6; ii++) {
        const int   b  = __shfl_sync(0xffffffffu, base, ii);
        const float wxb = __shfl_sync(0xffffffffu, wx, ii);
        const float wyb = __shfl_sync(0xffffffffu, wy, ii);
        const int i00 = b + lane;
        const __half2 a2 = g_planes2[i00];                   // (v00, v01)
        const __half2 b2 = g_planes2[i00 + PW[ii] * CCH];    // (v10, v11)
        const float2 fa = __half22float2(a2);
        const float2 fb = __half22float2(b2);
        const float r0 = fa.x + wxb * (fa.y - fa.x);
        const float r1 = fb.x + wxb * (fb.y - fb.x);
        prod *= r0 + wyb * (r1 - r0);
    }
    out[(size_t)warp * CCH + lane] = prod;
}

extern "C" void kernel_launch(void* const* d_in, const int* in_sizes, int n_in,
                              void* d_out, int out_size) {
    const float* pts = (const float*)d_in[0];
    const float* ts  = (const float*)d_in[1];
    CoefPtrs P;
    for (int i = 0; i < 6; i++) {
        P.yl[i]  = (const float*)d_in[2 + 3 * i];
        P.yha[i] = (const float*)d_in[3 + 3 * i];
        P.yhb[i] = (const float*)d_in[4 + 3 * i];
    }
    float* out = (float*)d_out;
    const int nPts = in_sizes[1];   // timestamps count = N

    // Opt-in to >48KB dynamic smem (host-side attribute set; not an alloc,
    // executes immediately even under graph capture; idempotent).
    const int SM12 = 2 * 128 * 64 * 4;   // 64 KB (largest plane)
    const int SM3  = 4 * 128 * 32 * 4;   // 64 KB
    cudaFuncSetAttribute(k_s12, cudaFuncAttributeMaxDynamicSharedMemorySize, SM12);
    cudaFuncSetAttribute(k_s3t, cudaFuncAttributeMaxDynamicSharedMemorySize, SM3);

    dim3 blk(256);
    k_s12<<<dim3(CCH, 6), blk, SM12>>>(P);           // block per (c, plane)
    k_s3t<<<dim3(4, CCH, 6), blk, SM3>>>(P);         // block per (xt, c, plane)
    k_stage4<<<dim3(256, 6), blk>>>();

    const int totalThreads = nPts * 32;
    k_sample<<<(totalThreads + 255) / 256, 256>>>(pts, ts, out, nPts);
}

// round 16
// speedup vs baseline: 1.0136x; 1.0136x over previous
#include <cuda_runtime.h>
#include <cuda_fp16.h>

// ---------------------------------------------------------------------------
// WavePlaneField: 6 planes reconstructed via 2-level inverse DWT (coif4,
// periodization), bilinear-sampled at N points, channelwise product.
//
// Phase 1 (4 kernels, R12-measured-best forms): paired-parity stages 1-3,
//   wrap-padded row-tiled stage 4 -> x-paired fp16 planes
//   (y,x,c) = half2(v[y,x,c], v[y,x+1,c]).
// Phase 2: warp-per-point sampler. Lanes 0-5 compute the 6 planes' coords in
//   parallel and stash {byte_off, wx, half2(wy,wy)} in smem; the plane loop
//   does 1 broadcast LDS.128 + 2 LDG(half2) + HFMA2 y-lerp + fp32 x-lerp.
// ---------------------------------------------------------------------------

#define CCH 32

// All planes have H=256. W per plane:
__constant__ int c_W[6]    = {256, 256, 64, 256, 64, 64};
__constant__ int c_POFF[6] = {0, 65536, 131072, 147456, 212992, 229376}; // pixel offsets

// coif4 reconstruction filters (24 taps)
__constant__ float REC_LO_C[24] = {
    0.0008923136685823146f, -0.0016294920126017326f, -0.0073461663276420935f,
    0.016068943964776348f, 0.026682300156053072f, -0.08126669968087875f,
    -0.05607731331675481f, 0.41530840703043026f, 0.782238930920499f,
    0.4343860564914685f, -0.06662747426342504f, -0.09622044203398798f,
    0.03933442712333749f, 0.025082261844864097f, -0.015211731527946259f,
    -0.00565828668661072f, 0.003751436157278457f, 0.0012665619292989445f,
    -0.0005890207562443383f, -0.00025997455248771324f, 6.233903446100713e-05f,
    3.1229875865345646e-05f, -3.2596802368833675e-06f, -1.7849850030882614e-06f
};
__constant__ float REC_HI_C[24] = {
    -1.7849850030882614e-06f, 3.2596802368833675e-06f, 3.1229875865345646e-05f,
    -6.233903446100713e-05f, -0.00025997455248771324f, 0.0005890207562443383f,
    0.0012665619292989445f, -0.003751436157278457f, -0.00565828668661072f,
    0.015211731527946259f, 0.025082261844864097f, -0.03933442712333749f,
    -0.09622044203398798f, 0.06662747426342504f, 0.4343860564914685f,
    -0.782238930920499f, 0.41530840703043026f, 0.05607731331675481f,
    -0.08126669968087875f, -0.026682300156053072f, 0.016068943964776348f,
    0.0073461663276420935f, -0.0016294920126017326f, -0.0008923136685823146f
};

// Scratch (static device globals; per-plane strides sized for the largest plane)
#define S_LO1 262144    // C*128*64
#define S_MID 524288    // C*128*128
#define S_LO2 1048576   // C*256*128
__device__ float g_lo1[6 * S_LO1];
__device__ float g_hi1[6 * S_LO1];
__device__ float g_mid[6 * S_MID];
__device__ float g_lo2[6 * S_LO2];
__device__ float g_hi2[6 * S_LO2];
// x-paired fp16 planes: [pixel][c] = half2(v[y,x,c], v[y,min(x+1,W-1),c])
__device__ __half2 g_planes2[245760 * CCH];

struct CoefPtrs {
    const float* yl[6];
    const float* yha[6];
    const float* yhb[6];
};

// Stage 1 (paired-parity): level-1 H-axis synthesis.
// in: yl[C,64,w4], yhb[C,3,64,w4] -> lo1,hi1 [C,128,w4]
__global__ void k_stage1(CoefPtrs P) {
    const int pl = blockIdx.y;
    const int w4 = c_W[pl] >> 2;
    const int n = CCH * 64 * w4;             // pairs
    const int tid = blockIdx.x * blockDim.x + threadIdx.x;
    if (tid >= n) return;
    const int x = tid % w4;
    const int s = (tid / w4) & 63;
    const int c = tid / (w4 * 64);
    const float* yl = P.yl[pl];
    const float* yhb = P.yhb[pl];
    const int bandStride = 64 * w4;
    float lo0 = 0.f, lo1v = 0.f, hi0 = 0.f, hi1v = 0.f;
#pragma unroll
    for (int m = 0; m < 12; m++) {
        int row = s - m; if (row < 0) row += 64;
        const float a  = yl [(c * 64 + row) * w4 + x];
        const int b0i  = ((c * 3 + 0) * 64 + row) * w4 + x;
        const float b0 = yhb[b0i];
        const float b1 = yhb[b0i + bandStride];
        const float b2 = yhb[b0i + 2 * bandStride];
        const float fl0 = REC_LO_C[2 * m],     fh0 = REC_HI_C[2 * m];
        const float fl1 = REC_LO_C[2 * m + 1], fh1 = REC_HI_C[2 * m + 1];
        lo0  += fl0 * a  + fh0 * b0;
        lo1v += fl1 * a  + fh1 * b0;
        hi0  += fl0 * b1 + fh0 * b2;
        hi1v += fl1 * b1 + fh1 * b2;
    }
    const int ob = pl * S_LO1 + (c * 128 + 2 * s) * w4 + x;
    g_lo1[ob]      = lo0;
    g_lo1[ob + w4] = lo1v;
    g_hi1[ob]      = hi0;
    g_hi1[ob + w4] = hi1v;
}

// Stage 2 (paired parity): level-1 W-axis synthesis.
// in: lo1,hi1 [C,128,w4] -> mid [C,128,w2]. One thread -> outputs j=2s,2s+1.
__global__ void k_stage2() {
    const int pl = blockIdx.y;
    const int w2 = c_W[pl] >> 1;
    const int w4 = w2 >> 1;
    const int n = CCH * 128 * w4;            // pairs
    const int tid = blockIdx.x * blockDim.x + threadIdx.x;
    if (tid >= n) return;
    const int s = tid % w4;
    const int i = (tid / w4) & 127;
    const int c = tid / (w4 * 128);
    const int base = pl * S_LO1 + (c * 128 + i) * w4;
    float v0 = 0.f, v1 = 0.f;
#pragma unroll
    for (int m = 0; m < 12; m++) {
        int col = s - m; if (col < 0) col += w4;
        const float lv = g_lo1[base + col];
        const float hv = g_hi1[base + col];
        v0 += REC_LO_C[2 * m]     * lv + REC_HI_C[2 * m]     * hv;
        v1 += REC_LO_C[2 * m + 1] * lv + REC_HI_C[2 * m + 1] * hv;
    }
    const int ob = pl * S_MID + (c * 128 + i) * w2 + 2 * s;
    g_mid[ob]     = v0;
    g_mid[ob + 1] = v1;
}

// Stage 3 (paired-parity): level-2 H-axis synthesis.
// in: mid [C,128,w2], yha [C,3,128,w2] -> lo2,hi2 [C,256,w2]
__global__ void k_stage3(CoefPtrs P) {
    const int pl = blockIdx.y;
    const int w2 = c_W[pl] >> 1;
    const int n = CCH * 128 * w2;            // pairs
    const int tid = blockIdx.x * blockDim.x + threadIdx.x;
    if (tid >= n) return;
    const int x = tid % w2;
    const int s = (tid / w2) & 127;
    const int c = tid / (w2 * 128);
    const float* yha = P.yha[pl];
    const int bandStride = 128 * w2;
    const float* midP = g_mid + pl * S_MID;
    float lo0 = 0.f, lo1v = 0.f, hi0 = 0.f, hi1v = 0.f;
#pragma unroll
    for (int m = 0; m < 12; m++) {
        int row = s - m; if (row < 0) row += 128;
        const float mv = midP[(c * 128 + row) * w2 + x];
        const int a0i  = ((c * 3 + 0) * 128 + row) * w2 + x;
        const float a0 = yha[a0i];
        const float a1 = yha[a0i + bandStride];
        const float a2 = yha[a0i + 2 * bandStride];
        const float fl0 = REC_LO_C[2 * m],     fh0 = REC_HI_C[2 * m];
        const float fl1 = REC_LO_C[2 * m + 1], fh1 = REC_HI_C[2 * m + 1];
        lo0  += fl0 * mv + fh0 * a0;
        lo1v += fl1 * mv + fh1 * a0;
        hi0  += fl0 * a1 + fh0 * a2;
        hi1v += fl1 * a1 + fh1 * a2;
    }
    const int ob = pl * S_LO2 + (c * 256 + 2 * s) * w2 + x;
    g_lo2[ob]      = lo0;
    g_lo2[ob + w2] = lo1v;
    g_hi2[ob]      = hi0;
    g_hi2[ob + w2] = hi1v;
}

// Stage 4 (row-tiled, paired-parity, wrap-padded smem, x-paired output):
// level-2 W-axis synthesis + transpose to x-paired half2 layout.
__global__ void __launch_bounds__(256) k_stage4() {
    const int pl = blockIdx.y;
    const int W = c_W[pl];
    const int w2 = W >> 1;
    const int y = blockIdx.x;

    __shared__ float lo_s[32][141];    // [c][11 wrap pads | w2 cols]
    __shared__ float hi_s[32][141];
    __shared__ float out_s[256][33];   // [x][c]

    const int sh = (w2 == 128) ? 7 : 5;          // log2(w2)
    const int rowBase = pl * S_LO2 + y * w2;     // + c*256*w2 per channel
    for (int t = threadIdx.x; t < 32 * w2; t += 256) {
        const int c = t >> sh;
        const int col = t & (w2 - 1);
        const int gi = rowBase + c * (256 * w2) + col;
        lo_s[c][11 + col] = g_lo2[gi];
        hi_s[c][11 + col] = g_hi2[gi];
    }
    // wrap pads: k=0..10 holds logical col w2-11+k
    for (int t = threadIdx.x; t < 32 * 11; t += 256) {
        const int c = t / 11;
        const int k = t % 11;
        const int gi = rowBase + c * (256 * w2) + (w2 - 11 + k);
        lo_s[c][k] = g_lo2[gi];
        hi_s[c][k] = g_hi2[gi];
    }
    __syncthreads();

    const int nPairs = w2 * CCH;                  // one thread -> 2 outputs
    for (int t = threadIdx.x; t < nPairs; t += 256) {
        const int c = t & 31;
        const int s = t >> 5;
        const float* lp = &lo_s[c][11 + s];       // taps at lp[-m]
        const float* hp = &hi_s[c][11 + s];
        float v0 = 0.f, v1 = 0.f;                 // parity 0 / parity 1
#pragma unroll
        for (int m = 0; m < 12; m++) {
            const float lv = lp[-m];
            const float hv = hp[-m];
            v0 += REC_LO_C[2 * m]     * lv + REC_HI_C[2 * m]     * hv;
            v1 += REC_LO_C[2 * m + 1] * lv + REC_HI_C[2 * m + 1] * hv;
        }
        out_s[2 * s][c]     = v0;
        out_s[2 * s + 1][c] = v1;
    }
    __syncthreads();

    __half2* __restrict__ outRow = g_planes2 + ((size_t)(c_POFF[pl] + y * W)) * CCH;
    const int n = W * CCH;
    for (int t = threadIdx.x; t < n; t += 256) {
        const int c = t & 31;
        const int x = t >> 5;
        const int x1 = (x + 1 < W) ? x + 1 : W - 1;
        outRow[x * CCH + c] = __floats2half2_rn(out_s[x][c], out_s[x1][c]);
    }
}

// Phase 2: warp per point, lane = channel. Lanes 0-5 compute the 6 planes'
// coords in parallel and stash {byte_off, wx, half2(wy,wy)} in smem; loop
// does 1 broadcast LDS.128 + 2 half2 LDG + HFMA2 y-lerp + fp32 x-lerp.
__global__ void __launch_bounds__(256) k_sample(const float* __restrict__ pts,
                                                const float* __restrict__ ts,
                                                float* __restrict__ out,
                                                int nPts) {
    __shared__ float4 cdS[8][6];      // per-warp coord records
    const int wInB = threadIdx.x >> 5;
    const int warp = (blockIdx.x * blockDim.x + threadIdx.x) >> 5;
    const int lane = threadIdx.x & 31;
    if (warp >= nPts) return;

    const float inv = -1.0f / 1.3f;   // pts_n = -pts/B
    const float p0 = pts[warp * 3 + 0] * inv;
    const float p1 = pts[warp * 3 + 1] * inv;
    const float p2 = pts[warp * 3 + 2] * inv;
    const float p3 = ts[warp] * 2.0f - 1.0f;

    // Per-lane plane coords (lanes 0-5 meaningful):
    // QIDX = {0,0,3,1,3,3} -> cx; RIDX = {1,2,0,2,1,2} -> cy
    const float cx = (lane < 2) ? p0 : ((lane == 3) ? p1 : p3);
    const float cy = (lane == 0 || lane == 4) ? p1
                   : ((lane == 2) ? p0 : p2);
    // W per plane {256,256,64,256,64,64}
    const bool small = (lane == 2 || lane >= 4);
    const float Wm1 = small ? 63.0f : 255.0f;
    const int   Wi  = small ? 64 : 256;
    const int   poff = c_POFF[(lane < 6) ? lane : 0];

    float xf = fminf(fmaxf((cx + 1.0f) * 0.5f * Wm1, 0.0f), Wm1);
    float yf = fminf(fmaxf((cy + 1.0f) * 0.5f * 255.0f, 0.0f), 255.0f);
    float x0f = fminf(floorf(xf), Wm1 - 1.0f);   // xf >= 0 already
    float y0f = fminf(floorf(yf), 254.0f);
    const float wx = xf - x0f;
    const float wy = yf - y0f;
    // byte offset of pixel (128 B per pixel: 32 channels x half2)
    const int boff = (poff + (int)y0f * Wi + (int)x0f) << 7;
    const __half2 wy2h = __floats2half2_rn(wy, wy);
    unsigned wy2u; *reinterpret_cast<__half2*>(&wy2u) = wy2h;

    if (lane < 6)
        cdS[wInB][lane] = make_float4(__int_as_float(boff), wx,
                                      __uint_as_float(wy2u), 0.0f);
    __syncwarp();

    constexpr int ROWB[6] = {256 * 128, 256 * 128, 64 * 128,
                             256 * 128, 64 * 128, 64 * 128};
    const char* __restrict__ pbase = (const char*)g_planes2 + (lane << 2);

    float prod = 1.0f;
#pragma unroll
    for (int ii = 0; ii < 6; ii++) {
        const float4 cd = cdS[wInB][ii];                 // broadcast LDS.128
        const char* pp = pbase + __float_as_int(cd.x);
        const __half2 a2 = *(const __half2*)pp;                     // (v00,v01)
        const __half2 b2 = *(const __half2*)(pp + ROWB[ii]);        // (v10,v11)
        unsigned wu = __float_as_uint(cd.z);
        const __half2 wyv = *reinterpret_cast<const __half2*>(&wu);
        // y-lerp both x-corners at once in fp16
        const __half2 c2 = __hfma2(wyv, __hsub2(b2, a2), a2);
        // x-lerp in fp32
        const float lo = __low2float(c2);
        const float hi = __high2float(c2);
        prod *= lo + cd.y * (hi - lo);
    }
    out[(size_t)warp * CCH + lane] = prod;
}

extern "C" void kernel_launch(void* const* d_in, const int* in_sizes, int n_in,
                              void* d_out, int out_size) {
    const float* pts = (const float*)d_in[0];
    const float* ts  = (const float*)d_in[1];
    CoefPtrs P;
    for (int i = 0; i < 6; i++) {
        P.yl[i]  = (const float*)d_in[2 + 3 * i];
        P.yha[i] = (const float*)d_in[3 + 3 * i];
        P.yhb[i] = (const float*)d_in[4 + 3 * i];
    }
    float* out = (float*)d_out;
    const int nPts = in_sizes[1];   // timestamps count = N

    dim3 blk(256);
    k_stage1<<<dim3((CCH * 64 * 64 + 255) / 256, 6), blk>>>(P);    // pairs, w4 max 64
    k_stage2<<<dim3((CCH * 128 * 64 + 255) / 256, 6), blk>>>();    // pairs, w4 max 64
    k_stage3<<<dim3((CCH * 128 * 128 + 255) / 256, 6), blk>>>(P);  // pairs, w2 max 128
    k_stage4<<<dim3(256, 6), blk>>>();

    const int totalThreads = nPts * 32;
    k_sample<<<(totalThreads + 255) / 256, 256>>>(pts, ts, out, nPts);
}

// round 17
// speedup vs baseline: 1.1675x; 1.1518x over previous
#include <cuda_runtime.h>
#include <cuda_fp16.h>

// ---------------------------------------------------------------------------
// WavePlaneField: 6 planes reconstructed via 2-level inverse DWT (coif4,
// periodization), bilinear-sampled at N points, channelwise product.
//
// Phase 1 (4 kernels, R12-measured-best forms): paired-parity stages 1-3,
//   wrap-padded row-tiled stage 4 -> x-paired fp16 planes
//   (y,x,c) = half2(v[y,x,c], v[y,x+1,c]).
// Phase 2: warp-per-TWO-points sampler. Lanes 0-5 compute point A's plane
//   coords, lanes 8-13 point B's (coord math executes once for both);
//   shfl broadcast; two independent load/lerp chains -> 2x ILP/MLP.
// ---------------------------------------------------------------------------

#define CCH 32

// All planes have H=256. W per plane:
__constant__ int c_W[6]    = {256, 256, 64, 256, 64, 64};
__constant__ int c_POFF[6] = {0, 65536, 131072, 147456, 212992, 229376}; // pixel offsets

// coif4 reconstruction filters (24 taps)
__constant__ float REC_LO_C[24] = {
    0.0008923136685823146f, -0.0016294920126017326f, -0.0073461663276420935f,
    0.016068943964776348f, 0.026682300156053072f, -0.08126669968087875f,
    -0.05607731331675481f, 0.41530840703043026f, 0.782238930920499f,
    0.4343860564914685f, -0.06662747426342504f, -0.09622044203398798f,
    0.03933442712333749f, 0.025082261844864097f, -0.015211731527946259f,
    -0.00565828668661072f, 0.003751436157278457f, 0.0012665619292989445f,
    -0.0005890207562443383f, -0.00025997455248771324f, 6.233903446100713e-05f,
    3.1229875865345646e-05f, -3.2596802368833675e-06f, -1.7849850030882614e-06f
};
__constant__ float REC_HI_C[24] = {
    -1.7849850030882614e-06f, 3.2596802368833675e-06f, 3.1229875865345646e-05f,
    -6.233903446100713e-05f, -0.00025997455248771324f, 0.0005890207562443383f,
    0.0012665619292989445f, -0.003751436157278457f, -0.00565828668661072f,
    0.015211731527946259f, 0.025082261844864097f, -0.03933442712333749f,
    -0.09622044203398798f, 0.06662747426342504f, 0.4343860564914685f,
    -0.782238930920499f, 0.41530840703043026f, 0.05607731331675481f,
    -0.08126669968087875f, -0.026682300156053072f, 0.016068943964776348f,
    0.0073461663276420935f, -0.0016294920126017326f, -0.0008923136685823146f
};

// Scratch (static device globals; per-plane strides sized for the largest plane)
#define S_LO1 262144    // C*128*64
#define S_MID 524288    // C*128*128
#define S_LO2 1048576   // C*256*128
__device__ float g_lo1[6 * S_LO1];
__device__ float g_hi1[6 * S_LO1];
__device__ float g_mid[6 * S_MID];
__device__ float g_lo2[6 * S_LO2];
__device__ float g_hi2[6 * S_LO2];
// x-paired fp16 planes: [pixel][c] = half2(v[y,x,c], v[y,min(x+1,W-1),c])
__device__ __half2 g_planes2[245760 * CCH];

struct CoefPtrs {
    const float* yl[6];
    const float* yha[6];
    const float* yhb[6];
};

// Stage 1 (paired-parity): level-1 H-axis synthesis.
// in: yl[C,64,w4], yhb[C,3,64,w4] -> lo1,hi1 [C,128,w4]
__global__ void k_stage1(CoefPtrs P) {
    const int pl = blockIdx.y;
    const int w4 = c_W[pl] >> 2;
    const int n = CCH * 64 * w4;             // pairs
    const int tid = blockIdx.x * blockDim.x + threadIdx.x;
    if (tid >= n) return;
    const int x = tid % w4;
    const int s = (tid / w4) & 63;
    const int c = tid / (w4 * 64);
    const float* yl = P.yl[pl];
    const float* yhb = P.yhb[pl];
    const int bandStride = 64 * w4;
    float lo0 = 0.f, lo1v = 0.f, hi0 = 0.f, hi1v = 0.f;
#pragma unroll
    for (int m = 0; m < 12; m++) {
        int row = s - m; if (row < 0) row += 64;
        const float a  = yl [(c * 64 + row) * w4 + x];
        const int b0i  = ((c * 3 + 0) * 64 + row) * w4 + x;
        const float b0 = yhb[b0i];
        const float b1 = yhb[b0i + bandStride];
        const float b2 = yhb[b0i + 2 * bandStride];
        const float fl0 = REC_LO_C[2 * m],     fh0 = REC_HI_C[2 * m];
        const float fl1 = REC_LO_C[2 * m + 1], fh1 = REC_HI_C[2 * m + 1];
        lo0  += fl0 * a  + fh0 * b0;
        lo1v += fl1 * a  + fh1 * b0;
        hi0  += fl0 * b1 + fh0 * b2;
        hi1v += fl1 * b1 + fh1 * b2;
    }
    const int ob = pl * S_LO1 + (c * 128 + 2 * s) * w4 + x;
    g_lo1[ob]      = lo0;
    g_lo1[ob + w4] = lo1v;
    g_hi1[ob]      = hi0;
    g_hi1[ob + w4] = hi1v;
}

// Stage 2 (paired parity): level-1 W-axis synthesis.
// in: lo1,hi1 [C,128,w4] -> mid [C,128,w2]. One thread -> outputs j=2s,2s+1.
__global__ void k_stage2() {
    const int pl = blockIdx.y;
    const int w2 = c_W[pl] >> 1;
    const int w4 = w2 >> 1;
    const int n = CCH * 128 * w4;            // pairs
    const int tid = blockIdx.x * blockDim.x + threadIdx.x;
    if (tid >= n) return;
    const int s = tid % w4;
    const int i = (tid / w4) & 127;
    const int c = tid / (w4 * 128);
    const int base = pl * S_LO1 + (c * 128 + i) * w4;
    float v0 = 0.f, v1 = 0.f;
#pragma unroll
    for (int m = 0; m < 12; m++) {
        int col = s - m; if (col < 0) col += w4;
        const float lv = g_lo1[base + col];
        const float hv = g_hi1[base + col];
        v0 += REC_LO_C[2 * m]     * lv + REC_HI_C[2 * m]     * hv;
        v1 += REC_LO_C[2 * m + 1] * lv + REC_HI_C[2 * m + 1] * hv;
    }
    const int ob = pl * S_MID + (c * 128 + i) * w2 + 2 * s;
    g_mid[ob]     = v0;
    g_mid[ob + 1] = v1;
}

// Stage 3 (paired-parity): level-2 H-axis synthesis.
// in: mid [C,128,w2], yha [C,3,128,w2] -> lo2,hi2 [C,256,w2]
__global__ void k_stage3(CoefPtrs P) {
    const int pl = blockIdx.y;
    const int w2 = c_W[pl] >> 1;
    const int n = CCH * 128 * w2;            // pairs
    const int tid = blockIdx.x * blockDim.x + threadIdx.x;
    if (tid >= n) return;
    const int x = tid % w2;
    const int s = (tid / w2) & 127;
    const int c = tid / (w2 * 128);
    const float* yha = P.yha[pl];
    const int bandStride = 128 * w2;
    const float* midP = g_mid + pl * S_MID;
    float lo0 = 0.f, lo1v = 0.f, hi0 = 0.f, hi1v = 0.f;
#pragma unroll
    for (int m = 0; m < 12; m++) {
        int row = s - m; if (row < 0) row += 128;
        const float mv = midP[(c * 128 + row) * w2 + x];
        const int a0i  = ((c * 3 + 0) * 128 + row) * w2 + x;
        const float a0 = yha[a0i];
        const float a1 = yha[a0i + bandStride];
        const float a2 = yha[a0i + 2 * bandStride];
        const float fl0 = REC_LO_C[2 * m],     fh0 = REC_HI_C[2 * m];
        const float fl1 = REC_LO_C[2 * m + 1], fh1 = REC_HI_C[2 * m + 1];
        lo0  += fl0 * mv + fh0 * a0;
        lo1v += fl1 * mv + fh1 * a0;
        hi0  += fl0 * a1 + fh0 * a2;
        hi1v += fl1 * a1 + fh1 * a2;
    }
    const int ob = pl * S_LO2 + (c * 256 + 2 * s) * w2 + x;
    g_lo2[ob]      = lo0;
    g_lo2[ob + w2] = lo1v;
    g_hi2[ob]      = hi0;
    g_hi2[ob + w2] = hi1v;
}

// Stage 4 (row-tiled, paired-parity, wrap-padded smem, x-paired output):
// level-2 W-axis synthesis + transpose to x-paired half2 layout.
__global__ void __launch_bounds__(256) k_stage4() {
    const int pl = blockIdx.y;
    const int W = c_W[pl];
    const int w2 = W >> 1;
    const int y = blockIdx.x;

    __shared__ float lo_s[32][141];    // [c][11 wrap pads | w2 cols]
    __shared__ float hi_s[32][141];
    __shared__ float out_s[256][33];   // [x][c]

    const int sh = (w2 == 128) ? 7 : 5;          // log2(w2)
    const int rowBase = pl * S_LO2 + y * w2;     // + c*256*w2 per channel
    for (int t = threadIdx.x; t < 32 * w2; t += 256) {
        const int c = t >> sh;
        const int col = t & (w2 - 1);
        const int gi = rowBase + c * (256 * w2) + col;
        lo_s[c][11 + col] = g_lo2[gi];
        hi_s[c][11 + col] = g_hi2[gi];
    }
    // wrap pads: k=0..10 holds logical col w2-11+k
    for (int t = threadIdx.x; t < 32 * 11; t += 256) {
        const int c = t / 11;
        const int k = t % 11;
        const int gi = rowBase + c * (256 * w2) + (w2 - 11 + k);
        lo_s[c][k] = g_lo2[gi];
        hi_s[c][k] = g_hi2[gi];
    }
    __syncthreads();

    const int nPairs = w2 * CCH;                  // one thread -> 2 outputs
    for (int t = threadIdx.x; t < nPairs; t += 256) {
        const int c = t & 31;
        const int s = t >> 5;
        const float* lp = &lo_s[c][11 + s];       // taps at lp[-m]
        const float* hp = &hi_s[c][11 + s];
        float v0 = 0.f, v1 = 0.f;                 // parity 0 / parity 1
#pragma unroll
        for (int m = 0; m < 12; m++) {
            const float lv = lp[-m];
            const float hv = hp[-m];
            v0 += REC_LO_C[2 * m]     * lv + REC_HI_C[2 * m]     * hv;
            v1 += REC_LO_C[2 * m + 1] * lv + REC_HI_C[2 * m + 1] * hv;
        }
        out_s[2 * s][c]     = v0;
        out_s[2 * s + 1][c] = v1;
    }
    __syncthreads();

    __half2* __restrict__ outRow = g_planes2 + ((size_t)(c_POFF[pl] + y * W)) * CCH;
    const int n = W * CCH;
    for (int t = threadIdx.x; t < n; t += 256) {
        const int c = t & 31;
        const int x = t >> 5;
        const int x1 = (x + 1 < W) ? x + 1 : W - 1;
        outRow[x * CCH + c] = __floats2half2_rn(out_s[x][c], out_s[x1][c]);
    }
}

// Phase 2: warp per TWO points, lane = channel. Lanes 0-5 compute point A's
// plane coords, lanes 8-13 point B's (one pass of clamp/floor math serves
// both). shfl broadcasts (base, wx, wy) from lane ii (A) and 8+ii (B); the
// two load/lerp chains are independent -> 2x ILP/MLP per warp.
__global__ void __launch_bounds__(256) k_sample(const float* __restrict__ pts,
                                                const float* __restrict__ ts,
                                                float* __restrict__ out,
                                                int nPts) {
    const int warp = (blockIdx.x * blockDim.x + threadIdx.x) >> 5;
    const int lane = threadIdx.x & 31;
    const int pA = warp * 2;
    const int pB = pA + 1;
    if (pA >= nPts) return;
    const bool hasB = (pB < nPts);

    // Lanes >= 8 work on point B (fall back to A if B out of range).
    const int pt = (lane >= 8 && hasB) ? pB : pA;
    const float inv = -1.0f / 1.3f;   // pts_n = -pts/B
    const float p0 = pts[pt * 3 + 0] * inv;
    const float p1 = pts[pt * 3 + 1] * inv;
    const float p2 = pts[pt * 3 + 2] * inv;
    const float p3 = ts[pt] * 2.0f - 1.0f;

    // Plane id within this point's lane group (0-5 meaningful):
    const int pl = lane & 7;
    // QIDX = {0,0,3,1,3,3} -> cx; RIDX = {1,2,0,2,1,2} -> cy
    const float cx = (pl < 2) ? p0 : ((pl == 3) ? p1 : p3);
    const float cy = (pl == 0 || pl == 4) ? p1
                   : ((pl == 2) ? p0 : p2);
    // W per plane {256,256,64,256,64,64}
    const bool small = (pl == 2 || pl >= 4);
    const float Wm1 = small ? 63.0f : 255.0f;
    const int   Wi  = small ? 64 : 256;
    const int   poff = c_POFF[(pl < 6) ? pl : 0];

    float xf = fminf(fmaxf((cx + 1.0f) * 0.5f * Wm1, 0.0f), Wm1);
    float yf = fminf(fmaxf((cy + 1.0f) * 0.5f * 255.0f, 0.0f), 255.0f);
    float x0f = fminf(floorf(xf), Wm1 - 1.0f);   // xf >= 0 already
    float y0f = fminf(floorf(yf), 254.0f);
    const float wx = xf - x0f;
    const float wy = yf - y0f;
    const int  base = (poff + (int)y0f * Wi + (int)x0f) * CCH;

    constexpr int PW[6] = {256, 256, 64, 256, 64, 64};

    float prodA = 1.0f, prodB = 1.0f;
#pragma unroll
    for (int ii = 0; ii < 6; ii++) {
        const int   bA  = __shfl_sync(0xffffffffu, base, ii);
        const float wxA = __shfl_sync(0xffffffffu, wx, ii);
        const float wyA = __shfl_sync(0xffffffffu, wy, ii);
        const int   bB  = __shfl_sync(0xffffffffu, base, 8 + ii);
        const float wxB = __shfl_sync(0xffffffffu, wx, 8 + ii);
        const float wyB = __shfl_sync(0xffffffffu, wy, 8 + ii);
        const int rs = PW[ii] * CCH;

        const int iA = bA + lane;
        const __half2 aA = g_planes2[iA];            // (v00, v01)
        const __half2 bA2 = g_planes2[iA + rs];      // (v10, v11)
        const int iB = bB + lane;
        const __half2 aB = g_planes2[iB];
        const __half2 bB2 = g_planes2[iB + rs];

        const float2 faA = __half22float2(aA);
        const float2 fbA = __half22float2(bA2);
        const float r0A = faA.x + wxA * (faA.y - faA.x);
        const float r1A = fbA.x + wxA * (fbA.y - fbA.x);
        prodA *= r0A + wyA * (r1A - r0A);

        const float2 faB = __half22float2(aB);
        const float2 fbB = __half22float2(bB2);
        const float r0B = faB.x + wxB * (faB.y - faB.x);
        const float r1B = fbB.x + wxB * (fbB.y - fbB.x);
        prodB *= r0B + wyB * (r1B - r0B);
    }
    out[(size_t)pA * CCH + lane] = prodA;
    if (hasB) out[(size_t)pB * CCH + lane] = prodB;
}

extern "C" void kernel_launch(void* const* d_in, const int* in_sizes, int n_in,
                              void* d_out, int out_size) {
    const float* pts = (const float*)d_in[0];
    const float* ts  = (const float*)d_in[1];
    CoefPtrs P;
    for (int i = 0; i < 6; i++) {
        P.yl[i]  = (const float*)d_in[2 + 3 * i];
        P.yha[i] = (const float*)d_in[3 + 3 * i];
        P.yhb[i] = (const float*)d_in[4 + 3 * i];
    }
    float* out = (float*)d_out;
    const int nPts = in_sizes[1];   // timestamps count = N

    dim3 blk(256);
    k_stage1<<<dim3((CCH * 64 * 64 + 255) / 256, 6), blk>>>(P);    // pairs, w4 max 64
    k_stage2<<<dim3((CCH * 128 * 64 + 255) / 256, 6), blk>>>();    // pairs, w4 max 64
    k_stage3<<<dim3((CCH * 128 * 128 + 255) / 256, 6), blk>>>(P);  // pairs, w2 max 128
    k_stage4<<<dim3(256, 6), blk>>>();

    const int nWarps = (nPts + 1) / 2;
    const int totalThreads = nWarps * 32;
    k_sample<<<(totalThreads + 255) / 256, 256>>>(pts, ts, out, nPts);
}